// round 4
// baseline (speedup 1.0000x reference)
#include <cuda_runtime.h>
#include <math.h>

#define B_   128
#define T_   512
#define I_   64
#define H_   512
#define L_   64
#define DEC_ 100

typedef unsigned long long ull;

#define NBLK 128
#define NTHR 128
#define NBAR 715           // 1 + 512 + 1 + 1 + 200

// ---------------- device globals (no allocation allowed) ----------------
__device__ unsigned g_bar[1024];          // barrier slots (zero-init)
__device__ float g_h[2][B_ * H_];         // ping-pong hidden state
__device__ float g_z[B_ * L_];
__device__ float g_x[B_ * L_];

__device__ __forceinline__ float sigf(float v) { return 1.0f / (1.0f + expf(-v)); }

__device__ __forceinline__ void ffma2(ull& d, ull a, ull b) {
    asm("fma.rn.f32x2 %0, %1, %2, %0;" : "+l"(d) : "l"(a), "l"(b));
}
__device__ __forceinline__ ull dupf(float v) {
    unsigned u = __float_as_uint(v);
    return ((ull)u << 32) | (ull)u;
}

// ---------------- software grid barrier ----------------
// All 128 blocks are co-resident (1 block/SM, 128 <= 148 SMs). Monotonic
// per-slot counters; slot idx-1 is reset by block 0 after passing slot idx
// (everyone provably passed idx-1). Slot NBAR-1 is reset at kernel start.
__device__ __forceinline__ void grid_bar(int idx, int tid, int bid)
{
    __threadfence();          // release this block's global writes
    __syncthreads();
    if (tid == 0) {
        atomicAdd(&g_bar[idx], 1u);
        volatile unsigned* p = &g_bar[idx];
        while (*p < (unsigned)NBLK) {}
        __threadfence();      // acquire
        if (bid == 0 && idx > 0) atomicExch(&g_bar[idx - 1], 0u);
    }
    __syncthreads();
}

// ---------------- smem layout (floats) ----------------
// Wt   : [576][36]            = 20736
// As_d : ull [64][64]         =  8192 floats (32 KB), Cs overlays it
// bsum : [32]
#define WT_STR   36
#define WT_FLTS  (576 * WT_STR)
#define ASD_OFF  WT_FLTS
#define BSUM_OFF (WT_FLTS + 8192)
#define SMEM_FLTS (WT_FLTS + 8192 + 32)
#define SMEM_BYTES (SMEM_FLTS * 4)

// ---------------- resident-weight loader (transposed) ----------------
__device__ __forceinline__ void load_weights(float* Wt, float* bsum,
    const float* __restrict__ Wih, const float* __restrict__ Whh,
    const float* __restrict__ bih, const float* __restrict__ bhh,
    int j0, int tid)
{
    __syncthreads();
    // Wih part: 32 rows x 64 k  -> Wt[k][r], k in [0,64)
    for (int q = tid; q < 32 * 16; q += NTHR) {
        int r = q >> 4, k4 = q & 15;
        int row = (r >> 3) * H_ + j0 + (r & 7);
        float4 v = *(const float4*)(Wih + row * I_ + k4 * 4);
        Wt[(k4 * 4 + 0) * WT_STR + r] = v.x;
        Wt[(k4 * 4 + 1) * WT_STR + r] = v.y;
        Wt[(k4 * 4 + 2) * WT_STR + r] = v.z;
        Wt[(k4 * 4 + 3) * WT_STR + r] = v.w;
    }
    // Whh part: 32 rows x 512 k -> Wt[64+k][r]
    for (int q = tid; q < 32 * 128; q += NTHR) {
        int r = q >> 7, k4 = q & 127;
        int row = (r >> 3) * H_ + j0 + (r & 7);
        float4 v = *(const float4*)(Whh + row * H_ + k4 * 4);
        Wt[(64 + k4 * 4 + 0) * WT_STR + r] = v.x;
        Wt[(64 + k4 * 4 + 1) * WT_STR + r] = v.y;
        Wt[(64 + k4 * 4 + 2) * WT_STR + r] = v.z;
        Wt[(64 + k4 * 4 + 3) * WT_STR + r] = v.w;
    }
    if (tid < 32) {
        int g = tid >> 3, jj = tid & 7;
        bsum[tid] = bih[g * H_ + j0 + jj] + bhh[g * H_ + j0 + jj];
    }
    __syncthreads();
}

// ---------------- fused GEMM + cell update for one LSTM step ----------------
// Block tile: 64 batch x 32 gate-cols (all 4 gates of 8 hidden units).
// 128 threads, microtile 4m x 4n, f32x2 paired across n.
__device__ __forceinline__ void gemm_cell_step(
    const float* __restrict__ xsrc, int xld,
    const float* __restrict__ hsrc,
    float* __restrict__ hdst,
    const float* Wt, ull* As_d, float* Cs, const float* bsum,
    float* c_reg, int m0, int j0, int tid, int tx, int ty)
{
    ull acc[4][2];
#pragma unroll
    for (int i = 0; i < 4; ++i) { acc[i][0] = 0ull; acc[i][1] = 0ull; }

    float4 st[8];
    // prefetch tile 0 (input part)
#pragma unroll
    for (int i = 0; i < 8; ++i) {
        int idx = tid + i * NTHR;
        int m = idx >> 4, k4 = idx & 15;
        st[i] = *(const float4*)(xsrc + (m0 + m) * xld + k4 * 4);
    }

    for (int t = 0; t < 9; ++t) {
        // store staged A tile (duplicated, transposed [k][m])
#pragma unroll
        for (int i = 0; i < 8; ++i) {
            int idx = tid + i * NTHR;
            int m = idx >> 4, k4 = idx & 15;
            float4 v = st[i];
            As_d[(k4 * 4 + 0) * 64 + m] = dupf(v.x);
            As_d[(k4 * 4 + 1) * 64 + m] = dupf(v.y);
            As_d[(k4 * 4 + 2) * 64 + m] = dupf(v.z);
            As_d[(k4 * 4 + 3) * 64 + m] = dupf(v.w);
        }
        __syncthreads();
        // prefetch next tile (recurrent part, K offset t*64)
        if (t < 8) {
            const float* Ap = hsrc + t * 64;
#pragma unroll
            for (int i = 0; i < 8; ++i) {
                int idx = tid + i * NTHR;
                int m = idx >> 4, k4 = idx & 15;
                st[i] = *(const float4*)(Ap + (m0 + m) * H_ + k4 * 4);
            }
        }
        const float* wbase = Wt + (t * 64) * WT_STR + tx * 4;
#pragma unroll 8
        for (int k = 0; k < 64; ++k) {
            const ull* ar = As_d + k * 64 + ty * 4;
            ulonglong2 a01 = *(const ulonglong2*)ar;
            ulonglong2 a23 = *(const ulonglong2*)(ar + 2);
            ulonglong2 bb  = *(const ulonglong2*)(wbase + k * WT_STR);
            ffma2(acc[0][0], a01.x, bb.x); ffma2(acc[0][1], a01.x, bb.y);
            ffma2(acc[1][0], a01.y, bb.x); ffma2(acc[1][1], a01.y, bb.y);
            ffma2(acc[2][0], a23.x, bb.x); ffma2(acc[2][1], a23.x, bb.y);
            ffma2(acc[3][0], a23.y, bb.x); ffma2(acc[3][1], a23.y, bb.y);
        }
        __syncthreads();
    }

    // stage gates to Cs[m][n] (stride 33), overlays As_d
#pragma unroll
    for (int i = 0; i < 4; ++i)
#pragma unroll
        for (int p = 0; p < 2; ++p) {
            ull v = acc[i][p];
            Cs[(ty * 4 + i) * 33 + tx * 4 + p * 2 + 0] = __uint_as_float((unsigned)(v & 0xffffffffull));
            Cs[(ty * 4 + i) * 33 + tx * 4 + p * 2 + 1] = __uint_as_float((unsigned)(v >> 32));
        }
    __syncthreads();

    // cell update: 512 cells, 4 per thread, c lives in registers
#pragma unroll
    for (int w = 0; w < 4; ++w) {
        int idx = w * NTHR + tid;
        int m = idx >> 3, jj = idx & 7;
        float gi = Cs[m * 33 + jj]      + bsum[jj];
        float gf = Cs[m * 33 + 8 + jj]  + bsum[8 + jj];
        float gg = Cs[m * 33 + 16 + jj] + bsum[16 + jj];
        float go = Cs[m * 33 + 24 + jj] + bsum[24 + jj];
        float cn = sigf(gf) * c_reg[w] + sigf(gi) * tanhf(gg);
        float hn = sigf(go) * tanhf(cn);
        c_reg[w] = cn;
        hdst[(m0 + m) * H_ + j0 + jj] = hn;
    }
    __syncthreads();
}

// ---------------- the megakernel ----------------
__global__ void __launch_bounds__(NTHR, 1)
vae_mega(const float* __restrict__ seq,  const float* __restrict__ eps,
         const float* __restrict__ Wih_e, const float* __restrict__ Whh_e,
         const float* __restrict__ bih_e, const float* __restrict__ bhh_e,
         const float* __restrict__ Wm, const float* __restrict__ bm,
         const float* __restrict__ Wv, const float* __restrict__ bv,
         const float* __restrict__ Wi, const float* __restrict__ bi,
         const float* __restrict__ Wih_d, const float* __restrict__ Whh_d,
         const float* __restrict__ bih_d, const float* __restrict__ bhh_d,
         const float* __restrict__ Wo, const float* __restrict__ bo,
         float* __restrict__ out_xhat, float* __restrict__ out_mean,
         float* __restrict__ out_lv)
{
    extern __shared__ float smem[];
    float* Wt   = smem;
    ull*   As_d = (ull*)(smem + ASD_OFF);
    float* Cs   = (float*)As_d;
    float* bsum = smem + BSUM_OFF;

    const int tid = threadIdx.x;
    const int bid = blockIdx.x;
    const int tx  = tid & 7;
    const int ty  = tid >> 3;
    const int j0  = (bid >> 1) * 8;      // hidden slice
    const int m0  = (bid & 1) * 64;      // batch half
    const int gwarp = bid * 4 + (tid >> 5);
    const int lane  = tid & 31;

    int barid = 0;
    if (bid == 0 && tid == 0) atomicExch(&g_bar[NBAR - 1], 0u);

    float c_reg[4];

    // ===== encoder =====
    load_weights(Wt, bsum, Wih_e, Whh_e, bih_e, bhh_e, j0, tid);

    // init h(0)=0 slice, c=0
#pragma unroll
    for (int w = 0; w < 4; ++w) {
        int idx = w * NTHR + tid;
        int m = idx >> 3, jj = idx & 7;
        g_h[0][(m0 + m) * H_ + j0 + jj] = 0.0f;
        c_reg[w] = 0.0f;
    }
    grid_bar(barid++, tid, bid);

    for (int t = 0; t < T_; ++t) {
        gemm_cell_step(seq + t * I_, T_ * I_,
                       g_h[t & 1], g_h[(t + 1) & 1],
                       Wt, As_d, Cs, bsum, c_reg, m0, j0, tid, tx, ty);
        grid_bar(barid++, tid, bid);
    }
    // h_n in g_h[0]

    // ===== VAE =====
    {
        const float* hn = g_h[0];
        for (int o = 0; o < 16; ++o) {
            int idx = gwarp * 16 + o;            // 0..8191
            int b = idx >> 6, l = idx & 63;
            const float* hb = hn + b * H_;
            const float* wm = Wm + l * H_;
            const float* wv = Wv + l * H_;
            float sm = 0.0f, sv = 0.0f;
#pragma unroll 4
            for (int k = lane; k < H_; k += 32) {
                float hv = hb[k];
                sm += hv * wm[k];
                sv += hv * wv[k];
            }
#pragma unroll
            for (int off = 16; off > 0; off >>= 1) {
                sm += __shfl_down_sync(0xffffffffu, sm, off);
                sv += __shfl_down_sync(0xffffffffu, sv, off);
            }
            if (lane == 0) {
                sm += bm[l];
                sv += bv[l];
                out_mean[b * L_ + l] = sm;
                out_lv  [b * L_ + l] = sv;
                g_z[b * L_ + l] = sm + eps[b * L_ + l] * expf(0.5f * sv);
            }
        }
    }
    grid_bar(barid++, tid, bid);

    // ===== decoder init =====
    load_weights(Wt, bsum, Wih_d, Whh_d, bih_d, bhh_d, j0, tid);
    {
        int gt = bid * NTHR + tid;               // 0..16383
#pragma unroll
        for (int q = 0; q < 4; ++q) {
            int idx = q * 16384 + gt;            // 0..65535
            int b = idx >> 9, j = idx & 511;
            const float* zb = g_z + b * L_;
            const float* wr = Wi + j * L_;
            float s = bi[j];
#pragma unroll 16
            for (int k = 0; k < L_; ++k) s += zb[k] * wr[k];
            g_h[0][b * H_ + j] = s;
        }
        if (gt < B_ * L_) g_x[gt] = 0.0f;
#pragma unroll
        for (int w = 0; w < 4; ++w) c_reg[w] = 0.0f;
    }
    grid_bar(barid++, tid, bid);

    // ===== decoder loop =====
    for (int s = 0; s < DEC_; ++s) {
        gemm_cell_step(g_x, L_,
                       g_h[s & 1], g_h[(s + 1) & 1],
                       Wt, As_d, Cs, bsum, c_reg, m0, j0, tid, tx, ty);
        grid_bar(barid++, tid, bid);

        // out_proj: x = h @ Wo^T + bo  (512 warps x 16 outputs)
        const float* hcur = g_h[(s + 1) & 1];
        for (int o = 0; o < 16; ++o) {
            int idx = gwarp * 16 + o;            // 0..8191
            int b = idx >> 6, i = idx & 63;
            const float* hb = hcur + b * H_;
            const float* wr = Wo + i * H_;
            float sum = 0.0f;
#pragma unroll 4
            for (int k = lane; k < H_; k += 32) sum += hb[k] * wr[k];
#pragma unroll
            for (int off = 16; off > 0; off >>= 1)
                sum += __shfl_down_sync(0xffffffffu, sum, off);
            if (lane == 0) {
                float v = sum + bo[i];
                g_x[b * I_ + i] = v;
                out_xhat[(b * DEC_ + s) * I_ + i] = v;
            }
        }
        grid_bar(barid++, tid, bid);
    }
}

// ---------------- launch ----------------
extern "C" void kernel_launch(void* const* d_in, const int* in_sizes, int n_in,
                              void* d_out, int out_size)
{
    (void)in_sizes; (void)n_in; (void)out_size;

    const float* seq    = (const float*)d_in[0];
    // d_in[1] = seq_lengths (unused)
    const float* eps    = (const float*)d_in[2];
    const float* Wih_e  = (const float*)d_in[3];
    const float* Whh_e  = (const float*)d_in[4];
    const float* bih_e  = (const float*)d_in[5];
    const float* bhh_e  = (const float*)d_in[6];
    const float* Wm     = (const float*)d_in[7];
    const float* bm     = (const float*)d_in[8];
    const float* Wv     = (const float*)d_in[9];
    const float* bv     = (const float*)d_in[10];
    const float* Wi     = (const float*)d_in[11];
    const float* bi     = (const float*)d_in[12];
    const float* Wih_d  = (const float*)d_in[13];
    const float* Whh_d  = (const float*)d_in[14];
    const float* bih_d  = (const float*)d_in[15];
    const float* bhh_d  = (const float*)d_in[16];
    const float* Wo     = (const float*)d_in[17];
    const float* bo     = (const float*)d_in[18];

    float* out      = (float*)d_out;
    float* out_xhat = out;                      // [B, 100, I]
    float* out_mean = out + B_ * DEC_ * I_;     // [B, L]
    float* out_lv   = out_mean + B_ * L_;       // [B, L]

    cudaFuncSetAttribute(vae_mega, cudaFuncAttributeMaxDynamicSharedMemorySize,
                         SMEM_BYTES);

    vae_mega<<<NBLK, NTHR, SMEM_BYTES>>>(
        seq, eps,
        Wih_e, Whh_e, bih_e, bhh_e,
        Wm, bm, Wv, bv, Wi, bi,
        Wih_d, Whh_d, bih_d, bhh_d,
        Wo, bo,
        out_xhat, out_mean, out_lv);
}

// round 9
// speedup vs baseline: 2.5017x; 2.5017x over previous
#include <cuda_runtime.h>
#include <math.h>

#define B_   128
#define T_   512
#define I_   64
#define H_   512
#define L_   64
#define DEC_ 100

typedef unsigned long long ull;

#define NBLK 128
#define NTHR 256
#define NBAR 715           // 1 + 512 + 1 + 1 + 200

// ---------------- device globals ----------------
__device__ unsigned g_bar[1024];
__device__ float g_h[2][B_ * H_];
__device__ float g_z[B_ * L_];
__device__ float g_x[B_ * L_];

__device__ __forceinline__ float sigf(float v) { return 1.0f / (1.0f + expf(-v)); }

__device__ __forceinline__ void ffma2(ull& d, ull a, ull b) {
    asm("fma.rn.f32x2 %0, %1, %2, %0;" : "+l"(d) : "l"(a), "l"(b));
}

// ---------------- software grid barrier (128 co-resident blocks) ----------------
__device__ __forceinline__ void grid_bar(int idx, int tid, int bid)
{
    __threadfence();
    __syncthreads();
    if (tid == 0) {
        atomicAdd(&g_bar[idx], 1u);
        volatile unsigned* p = &g_bar[idx];
        while (*p < (unsigned)NBLK) {}
        __threadfence();
        if (bid == 0 && idx > 0) atomicExch(&g_bar[idx - 1], 0u);
    }
    __syncthreads();
}

// group-local barrier (4 warps = 128 threads), ids 1 and 2
__device__ __forceinline__ void bar_group(int g)
{
    asm volatile("bar.sync %0, %1;" :: "r"(g + 1), "r"(128) : "memory");
}

// ---------------- smem layout (floats) ----------------
// Ws  : [32 n][580]  natural [n][k] weight rows (k 0..63 = Wih, 64..575 = Whh)
// As0 : [64 m][64 k] chunk buffer group 0 (column-rotated)
// As1 : same, group 1
// Xs  : [64][33] split-K partials — DEDICATED (overlaying As1 raced with
//       group-1 warps still reading As1 in their final compute chunk)
// bsum: [32]
#define WS_STR   580
#define WS_OFF   0
#define AS0_OFF  (32 * WS_STR)                 // 18560
#define AS1_OFF  (AS0_OFF + 4096)              // 22656
#define XS_OFF   (AS1_OFF + 4096)              // 26752
#define BSUM_OFF (XS_OFF + 64 * 33)            // 28864
#define SMEM_FLTS (BSUM_OFF + 32)
#define SMEM_BYTES (SMEM_FLTS * 4)

// ---------------- resident weight loader (natural [n][k] layout) ----------------
__device__ __forceinline__ void load_weights(float* Ws, float* bsum,
    const float* __restrict__ Wih, const float* __restrict__ Whh,
    const float* __restrict__ bih, const float* __restrict__ bhh,
    int j0, int tid)
{
    __syncthreads();
    // Wih: 32 rows x 64 k
    for (int q = tid; q < 32 * 16; q += NTHR) {
        int r = q >> 4, k4 = q & 15;
        int row = (r >> 3) * H_ + j0 + (r & 7);
        *(float4*)(Ws + r * WS_STR + k4 * 4) = *(const float4*)(Wih + row * I_ + k4 * 4);
    }
    // Whh: 32 rows x 512 k -> cols 64..575
    for (int q = tid; q < 32 * 128; q += NTHR) {
        int r = q >> 7, k4 = q & 127;
        int row = (r >> 3) * H_ + j0 + (r & 7);
        *(float4*)(Ws + r * WS_STR + 64 + k4 * 4) = *(const float4*)(Whh + row * H_ + k4 * 4);
    }
    if (tid < 32) {
        int g = tid >> 3, jj = tid & 7;
        bsum[tid] = bih[g * H_ + j0 + jj] + bhh[g * H_ + j0 + jj];
    }
    __syncthreads();
}

// chunk t source: t==0 -> x (K=64), t>=1 -> h (K offset (t-1)*64)
__device__ __forceinline__ void chunk_src(int t,
    const float* xsrc, int xld, const float* hsrc,
    const float*& Ap, int& lda, int& koff)
{
    if (t == 0) { Ap = xsrc; lda = xld; koff = 0; }
    else        { Ap = hsrc; lda = H_;  koff = (t - 1) * 64; }
}

// ---------------- fused GEMM + cell update, split-K across 2 warp groups ----------------
// Tile: 64 batch x 32 gate-cols. Thread (ty,tx) in group g: microtile 4m x 4gates,
// m = 4*ty+i, gate col r = tx + 8*gate (jj = tx). f32x2 pairs along K.
__device__ __forceinline__ void gemm_cell_step(
    const float* __restrict__ xsrc, int xld,
    const float* __restrict__ hsrc,
    float* __restrict__ hdst,
    const float* Ws, float* As0, float* As1, float* Xs, const float* bsum,
    float* c_reg, int m0, int j0, int tid)
{
    const int w    = tid >> 5;
    const int g    = w >> 2;          // 0: chunks 0..4, 1: chunks 5..8
    const int gtid = tid & 127;
    const int tx   = gtid & 7;
    const int ty   = gtid >> 3;       // 0..15
    float* Af = g ? As1 : As0;
    const int cbeg = g ? 5 : 0;
    const int cend = g ? 9 : 5;

    ull acc[4][4];
#pragma unroll
    for (int i = 0; i < 4; ++i)
#pragma unroll
        for (int j = 0; j < 4; ++j) acc[i][j] = 0ull;

    float4 st[8];
    {   // prefetch first chunk
        const float* Ap; int lda, koff;
        chunk_src(cbeg, xsrc, xld, hsrc, Ap, lda, koff);
#pragma unroll
        for (int i = 0; i < 8; ++i) {
            int idx = gtid + i * 128;
            int m = idx >> 4, k4 = idx & 15;
            st[i] = *(const float4*)(Ap + (m0 + m) * lda + koff + k4 * 4);
        }
    }

    const int colbase = 8 * (ty & 7);
    const float* b0p = Ws + (tx +  0) * WS_STR;
    const float* b1p = Ws + (tx +  8) * WS_STR;
    const float* b2p = Ws + (tx + 16) * WS_STR;
    const float* b3p = Ws + (tx + 24) * WS_STR;

    for (int t = cbeg; t < cend; ++t) {
        bar_group(g);                      // previous chunk's compute done
        // store staged chunk (column-rotated by m>>2 to spread read banks)
#pragma unroll
        for (int i = 0; i < 8; ++i) {
            int idx = gtid + i * 128;
            int m = idx >> 4, k4 = idx & 15;
            int col = (k4 * 4 + 8 * ((m >> 2) & 7)) & 63;
            *(float4*)(Af + m * 64 + col) = st[i];
        }
        bar_group(g);
        if (t + 1 < cend) {                // prefetch next chunk
            const float* Ap; int lda, koff;
            chunk_src(t + 1, xsrc, xld, hsrc, Ap, lda, koff);
#pragma unroll
            for (int i = 0; i < 8; ++i) {
                int idx = gtid + i * 128;
                int m = idx >> 4, k4 = idx & 15;
                st[i] = *(const float4*)(Ap + (m0 + m) * lda + koff + k4 * 4);
            }
        }
        const int kb = t * 64;
        const float* a0p = Af + (4 * ty + 0) * 64;
        const float* a1p = Af + (4 * ty + 1) * 64;
        const float* a2p = Af + (4 * ty + 2) * 64;
        const float* a3p = Af + (4 * ty + 3) * 64;
#pragma unroll 8
        for (int kp = 0; kp < 32; ++kp) {
            int col = (2 * kp + colbase) & 63;
            ull a0 = *(const ull*)(a0p + col);
            ull a1 = *(const ull*)(a1p + col);
            ull a2 = *(const ull*)(a2p + col);
            ull a3 = *(const ull*)(a3p + col);
            ull b0 = *(const ull*)(b0p + kb + 2 * kp);
            ull b1 = *(const ull*)(b1p + kb + 2 * kp);
            ull b2 = *(const ull*)(b2p + kb + 2 * kp);
            ull b3 = *(const ull*)(b3p + kb + 2 * kp);
            ffma2(acc[0][0], a0, b0); ffma2(acc[0][1], a0, b1);
            ffma2(acc[0][2], a0, b2); ffma2(acc[0][3], a0, b3);
            ffma2(acc[1][0], a1, b0); ffma2(acc[1][1], a1, b1);
            ffma2(acc[1][2], a1, b2); ffma2(acc[1][3], a1, b3);
            ffma2(acc[2][0], a2, b0); ffma2(acc[2][1], a2, b1);
            ffma2(acc[2][2], a2, b2); ffma2(acc[2][3], a2, b3);
            ffma2(acc[3][0], a3, b0); ffma2(acc[3][1], a3, b1);
            ffma2(acc[3][2], a3, b2); ffma2(acc[3][3], a3, b3);
        }
    }

    // epilogue: lo+hi horizontal reduce
    float s[4][4];
#pragma unroll
    for (int i = 0; i < 4; ++i)
#pragma unroll
        for (int j = 0; j < 4; ++j) {
            ull v = acc[i][j];
            s[i][j] = __uint_as_float((unsigned)(v & 0xffffffffull))
                    + __uint_as_float((unsigned)(v >> 32));
        }

    if (g == 1) {   // publish group-1 partials (dedicated Xs: no conflict with As1)
#pragma unroll
        for (int i = 0; i < 4; ++i)
#pragma unroll
            for (int j = 0; j < 4; ++j)
                Xs[(4 * ty + i) * 33 + tx + 8 * j] = s[i][j];
    }
    __syncthreads();
    if (g == 0) {   // combine + cell update, c in registers
#pragma unroll
        for (int i = 0; i < 4; ++i) {
            int m = 4 * ty + i;
            float gi = s[i][0] + Xs[m * 33 + tx]      + bsum[tx];
            float gf = s[i][1] + Xs[m * 33 + tx + 8]  + bsum[8 + tx];
            float gg = s[i][2] + Xs[m * 33 + tx + 16] + bsum[16 + tx];
            float go = s[i][3] + Xs[m * 33 + tx + 24] + bsum[24 + tx];
            float cn = sigf(gf) * c_reg[i] + sigf(gi) * tanhf(gg);
            float hn = sigf(go) * tanhf(cn);
            c_reg[i] = cn;
            hdst[(m0 + m) * H_ + j0 + tx] = hn;
        }
    }
    __syncthreads();
}

// ---------------- the megakernel ----------------
__global__ void __launch_bounds__(NTHR, 1)
vae_mega(const float* __restrict__ seq,  const float* __restrict__ eps,
         const float* __restrict__ Wih_e, const float* __restrict__ Whh_e,
         const float* __restrict__ bih_e, const float* __restrict__ bhh_e,
         const float* __restrict__ Wm, const float* __restrict__ bm,
         const float* __restrict__ Wv, const float* __restrict__ bv,
         const float* __restrict__ Wi, const float* __restrict__ bi,
         const float* __restrict__ Wih_d, const float* __restrict__ Whh_d,
         const float* __restrict__ bih_d, const float* __restrict__ bhh_d,
         const float* __restrict__ Wo, const float* __restrict__ bo,
         float* __restrict__ out_xhat, float* __restrict__ out_mean,
         float* __restrict__ out_lv)
{
    extern __shared__ float smem[];
    float* Ws   = smem + WS_OFF;
    float* As0  = smem + AS0_OFF;
    float* As1  = smem + AS1_OFF;
    float* Xs   = smem + XS_OFF;
    float* bsum = smem + BSUM_OFF;

    const int tid = threadIdx.x;
    const int bid = blockIdx.x;
    const int j0  = (bid >> 1) * 8;
    const int m0  = (bid & 1) * 64;
    const int gwarp = bid * 8 + (tid >> 5);   // 0..1023
    const int lane  = tid & 31;

    int barid = 0;
    if (bid == 0 && tid == 0) atomicExch(&g_bar[NBAR - 1], 0u);

    float c_reg[4];

    // ===== encoder =====
    load_weights(Ws, bsum, Wih_e, Whh_e, bih_e, bhh_e, j0, tid);
#pragma unroll
    for (int q = 0; q < 2; ++q) {
        int idx = q * (NBLK * NTHR) + bid * NTHR + tid;
        if (idx < B_ * H_) g_h[0][idx] = 0.0f;
    }
#pragma unroll
    for (int i = 0; i < 4; ++i) c_reg[i] = 0.0f;
    grid_bar(barid++, tid, bid);

    for (int t = 0; t < T_; ++t) {
        gemm_cell_step(seq + t * I_, T_ * I_,
                       g_h[t & 1], g_h[(t + 1) & 1],
                       Ws, As0, As1, Xs, bsum, c_reg, m0, j0, tid);
        grid_bar(barid++, tid, bid);
    }
    // h_n in g_h[0]

    // ===== VAE =====
    {
        const float* hn = g_h[0];
        for (int o = 0; o < 8; ++o) {
            int idx = gwarp * 8 + o;             // 0..8191
            int b = idx >> 6, l = idx & 63;
            const float* hb = hn + b * H_;
            const float* wm = Wm + l * H_;
            const float* wv = Wv + l * H_;
            float sm = 0.0f, sv = 0.0f;
#pragma unroll 4
            for (int k = lane; k < H_; k += 32) {
                float hv = hb[k];
                sm += hv * wm[k];
                sv += hv * wv[k];
            }
#pragma unroll
            for (int off = 16; off > 0; off >>= 1) {
                sm += __shfl_down_sync(0xffffffffu, sm, off);
                sv += __shfl_down_sync(0xffffffffu, sv, off);
            }
            if (lane == 0) {
                sm += bm[l];
                sv += bv[l];
                out_mean[b * L_ + l] = sm;
                out_lv  [b * L_ + l] = sv;
                g_z[b * L_ + l] = sm + eps[b * L_ + l] * expf(0.5f * sv);
            }
        }
    }
    grid_bar(barid++, tid, bid);

    // ===== decoder init =====
    load_weights(Ws, bsum, Wih_d, Whh_d, bih_d, bhh_d, j0, tid);
    {
        int gt = bid * NTHR + tid;               // 0..32767
#pragma unroll
        for (int q = 0; q < 2; ++q) {
            int idx = q * 32768 + gt;            // 0..65535
            int b = idx >> 9, j = idx & 511;
            const float* zb = g_z + b * L_;
            const float* wr = Wi + j * L_;
            float s = bi[j];
#pragma unroll 16
            for (int k = 0; k < L_; ++k) s += zb[k] * wr[k];
            g_h[0][b * H_ + j] = s;
        }
        if (gt < B_ * L_) g_x[gt] = 0.0f;
#pragma unroll
        for (int i = 0; i < 4; ++i) c_reg[i] = 0.0f;
    }
    grid_bar(barid++, tid, bid);

    // ===== decoder loop =====
    for (int s = 0; s < DEC_; ++s) {
        gemm_cell_step(g_x, L_,
                       g_h[s & 1], g_h[(s + 1) & 1],
                       Ws, As0, As1, Xs, bsum, c_reg, m0, j0, tid);
        grid_bar(barid++, tid, bid);

        const float* hcur = g_h[(s + 1) & 1];
        for (int o = 0; o < 8; ++o) {
            int idx = gwarp * 8 + o;             // 0..8191
            int b = idx >> 6, i = idx & 63;
            const float* hb = hcur + b * H_;
            const float* wr = Wo + i * H_;
            float sum = 0.0f;
#pragma unroll 4
            for (int k = lane; k < H_; k += 32) sum += hb[k] * wr[k];
#pragma unroll
            for (int off = 16; off > 0; off >>= 1)
                sum += __shfl_down_sync(0xffffffffu, sum, off);
            if (lane == 0) {
                float v = sum + bo[i];
                g_x[b * I_ + i] = v;
                out_xhat[(b * DEC_ + s) * I_ + i] = v;
            }
        }
        grid_bar(barid++, tid, bid);
    }
}

// ---------------- launch ----------------
extern "C" void kernel_launch(void* const* d_in, const int* in_sizes, int n_in,
                              void* d_out, int out_size)
{
    (void)in_sizes; (void)n_in; (void)out_size;

    const float* seq    = (const float*)d_in[0];
    const float* eps    = (const float*)d_in[2];
    const float* Wih_e  = (const float*)d_in[3];
    const float* Whh_e  = (const float*)d_in[4];
    const float* bih_e  = (const float*)d_in[5];
    const float* bhh_e  = (const float*)d_in[6];
    const float* Wm     = (const float*)d_in[7];
    const float* bm     = (const float*)d_in[8];
    const float* Wv     = (const float*)d_in[9];
    const float* bv     = (const float*)d_in[10];
    const float* Wi     = (const float*)d_in[11];
    const float* bi     = (const float*)d_in[12];
    const float* Wih_d  = (const float*)d_in[13];
    const float* Whh_d  = (const float*)d_in[14];
    const float* bih_d  = (const float*)d_in[15];
    const float* bhh_d  = (const float*)d_in[16];
    const float* Wo     = (const float*)d_in[17];
    const float* bo     = (const float*)d_in[18];

    float* out      = (float*)d_out;
    float* out_xhat = out;
    float* out_mean = out + B_ * DEC_ * I_;
    float* out_lv   = out_mean + B_ * L_;

    cudaFuncSetAttribute(vae_mega, cudaFuncAttributeMaxDynamicSharedMemorySize,
                         SMEM_BYTES);

    vae_mega<<<NBLK, NTHR, SMEM_BYTES>>>(
        seq, eps,
        Wih_e, Whh_e, bih_e, bhh_e,
        Wm, bm, Wv, bv, Wi, bi,
        Wih_d, Whh_d, bih_d, bhh_d,
        Wo, bo,
        out_xhat, out_mean, out_lv);
}